// round 6
// baseline (speedup 1.0000x reference)
#include <cuda_runtime.h>
#include <cstdint>

// Problem constants (fixed shapes for this problem)
#define TT   128
#define NN   50000
#define EE   1600000
#define CIN  16
#define CH   32
#define COUTC 8
#define FULL 0xFFFFFFFFu

#define GETC(v,u) ((u)==0?(v).x:(u)==1?(v).y:(u)==2?(v).z:(v).w)

// ---------------- scratch (device globals; no runtime allocation) ----------
__device__ int   g_is64;
__device__ int   g_cnt_src[NN];
__device__ int   g_cnt_dst[NN];
__device__ int   g_cursor[NN];
__device__ int   g_off[NN + 1];
__device__ float g_dinv[NN];
__device__ int2  g_csr[EE];            // {src, w-bits}
__device__ float g_h[NN * CH];
__device__ float g_hR[NN * CH];
__device__ float g_Z[NN * CH];
__device__ float g_AXs[NN * CIN];      // agg(x_t) for the CURRENT step only

// read edge index element honoring detected dtype
__device__ __forceinline__ long long edge_at(const void* ei, size_t idx) {
    if (g_is64) return ((const long long*)ei)[idx];
    return (long long)((const int*)ei)[idx];
}

// ---------------- preprocessing ----------------

// launch 0: zero state + dtype detect (block 0)
__global__ void k_zero(const void* ei) {
    int i = blockIdx.x * blockDim.x + threadIdx.x;
    int stride = gridDim.x * blockDim.x;
    if (blockIdx.x == 0) {
        int bad = 0;
        for (int k = threadIdx.x; k < 1024; k += blockDim.x) {
            long long v = ((const long long*)ei)[k];
            if (v < 0 || v >= NN) bad = 1;
        }
        int anybad = __syncthreads_or(bad);
        if (threadIdx.x == 0) g_is64 = anybad ? 0 : 1;
    }
    for (int j = i; j < NN * CH; j += stride) {
        g_h[j] = 0.f;
        if (j < NN) { g_cnt_src[j] = 0; g_cnt_dst[j] = 0; g_cursor[j] = 0; }
    }
}

// launch 1: single block (1024 thr): degree count + dinv + exclusive scan.
// One-time ~150us; keeps k_gru_a at launch index 3 for ncu.
__global__ void k_prep(const void* __restrict__ ei, int E) {
    int tid = threadIdx.x;
    // ---- count (global atomics) ----
    for (int i = tid; i < E; i += 1024) {
        long long s = edge_at(ei, i);
        long long d = edge_at(ei, (size_t)E + i);
        if (s >= 0 && s < NN) atomicAdd(&g_cnt_src[(int)s], 1);
        if (d >= 0 && d < NN) atomicAdd(&g_cnt_dst[(int)d], 1);
    }
    __threadfence();
    __syncthreads();
    // ---- dinv ----
    for (int n = tid; n < NN; n += 1024) {
        int dsrc = g_cnt_src[n];
        g_dinv[n] = (dsrc > 0) ? rsqrtf((float)dsrc) : 0.f;
    }
    __syncthreads();
    // ---- exclusive scan of cnt_dst -> g_off ----
    __shared__ int s[1024];
    __shared__ int carry_s;
    if (tid == 0) carry_s = 0;
    __syncthreads();
    for (int base = 0; base < NN; base += 1024) {
        int i = base + tid;
        int v = (i < NN) ? g_cnt_dst[i] : 0;
        s[tid] = v;
        __syncthreads();
        for (int off = 1; off < 1024; off <<= 1) {
            int x = (tid >= off) ? s[tid - off] : 0;
            __syncthreads();
            s[tid] += x;
            __syncthreads();
        }
        if (i < NN) g_off[i] = carry_s + s[tid] - v;
        __syncthreads();
        if (tid == 0) carry_s += s[1023];
        __syncthreads();
    }
    if (tid == 0) g_off[NN] = carry_s;
}

// launch 2: fill CSR
__global__ void k_fill(const void* __restrict__ ei, int E) {
    int i = blockIdx.x * blockDim.x + threadIdx.x;
    if (i < E) {
        long long sl = edge_at(ei, i);
        long long dl = edge_at(ei, (size_t)E + i);
        if (sl < 0 || sl >= NN || dl < 0 || dl >= NN) return;
        int s = (int)sl, d = (int)dl;
        int pos = g_off[d] + atomicAdd(&g_cursor[d], 1);
        g_csr[pos] = make_int2(s, __float_as_int(-g_dinv[s] * g_dinv[d]));
    }
}

// ---------------- gather helpers (warp-uniform csr reads) -----------------

// agg over h only (used by k_gru_b)
__device__ __forceinline__ float gather_h(const float* __restrict__ src, int n, int lane) {
    int i = g_off[n], end = g_off[n + 1];
    float a0 = 0.f, a1 = 0.f, a2 = 0.f, a3 = 0.f;
    for (; i + 4 <= end; i += 4) {
        int2 e0 = g_csr[i], e1 = g_csr[i + 1], e2 = g_csr[i + 2], e3 = g_csr[i + 3];
        a0 += __int_as_float(e0.y) * src[e0.x * CH + lane];
        a1 += __int_as_float(e1.y) * src[e1.x * CH + lane];
        a2 += __int_as_float(e2.y) * src[e2.x * CH + lane];
        a3 += __int_as_float(e3.y) * src[e3.x * CH + lane];
    }
    for (; i < end; i++) {
        int2 e = g_csr[i];
        a0 += __int_as_float(e.y) * src[e.x * CH + lane];
    }
    return (a0 + a1) + (a2 + a3);
}

// fused agg over h (all lanes) AND x (lanes 0..15, channel lane&15)
__device__ __forceinline__ void gather_hx(const float* __restrict__ hsrc,
                                          const float* __restrict__ Xt,
                                          int n, int lane, bool lo, int cx,
                                          float& av, float& axv) {
    int i = g_off[n], end = g_off[n + 1];
    float a0 = 0.f, a1 = 0.f, ax0 = 0.f, ax1 = 0.f;
    for (; i + 4 <= end; i += 4) {
        int2 e0 = g_csr[i], e1 = g_csr[i + 1], e2 = g_csr[i + 2], e3 = g_csr[i + 3];
        float w0 = __int_as_float(e0.y), w1 = __int_as_float(e1.y);
        float w2 = __int_as_float(e2.y), w3 = __int_as_float(e3.y);
        a0 += w0 * hsrc[e0.x * CH + lane];
        a1 += w1 * hsrc[e1.x * CH + lane];
        a0 += w2 * hsrc[e2.x * CH + lane];
        a1 += w3 * hsrc[e3.x * CH + lane];
        if (lo) {
            ax0 += w0 * Xt[e0.x * CIN + cx];
            ax1 += w1 * Xt[e1.x * CIN + cx];
            ax0 += w2 * Xt[e2.x * CIN + cx];
            ax1 += w3 * Xt[e3.x * CIN + cx];
        }
    }
    for (; i < end; i++) {
        int2 e = g_csr[i];
        float w = __int_as_float(e.y);
        a0 += w * hsrc[e.x * CH + lane];
        if (lo) ax0 += w * Xt[e.x * CIN + cx];
    }
    av = a0 + a1;
    axv = ax0 + ax1;
}

// ---------------- recurrence kernels ----------------
// 256 thr = 8 warps/block. Warp handles a node PAIR. Lane = hidden channel.

__global__ void __launch_bounds__(256, 4) k_gru_a(
    int t, const float* __restrict__ X,
    const float* __restrict__ Wxz, const float* __restrict__ bxz,
    const float* __restrict__ Whz, const float* __restrict__ bhz,
    const float* __restrict__ Wxr, const float* __restrict__ bxr,
    const float* __restrict__ Whr, const float* __restrict__ bhr)
{
    __shared__ float4 s_wx[CIN * CH];   // {wxz0, wxz1, wxr0, wxr1}[c][j]
    __shared__ float4 s_wh[CH * CH];    // {whz0, whz1, whr0, whr1}[c][j]
    __shared__ float  s_bz[CH], s_br[CH];
    __shared__ __align__(16) float s_st[8][6][CH];  // [warp][hA,aA,hB,aB,xpA,xpB]
    int tid = threadIdx.x;
    for (int i = tid; i < CIN * CH; i += 256)
        s_wx[i] = make_float4(Wxz[i], Wxz[CIN * CH + i], Wxr[i], Wxr[CIN * CH + i]);
    for (int i = tid; i < CH * CH; i += 256)
        s_wh[i] = make_float4(Whz[i], Whz[CH * CH + i], Whr[i], Whr[CH * CH + i]);
    if (tid < CH) { s_bz[tid] = bxz[tid] + bhz[tid]; s_br[tid] = bxr[tid] + bhr[tid]; }
    __syncthreads();

    const float* Xt = X + (size_t)t * NN * CIN;
    int lane = tid & 31, wid = tid >> 5;
    bool lo = lane < 16;
    int cx = lane & 15;
    int gw = blockIdx.x * 8 + wid, nw = gridDim.x * 8;
    for (int p = gw; p < NN / 2; p += nw) {
        int nA = 2 * p, nB = 2 * p + 1;
        float hA = g_h[nA * CH + lane];
        float hB = g_h[nB * CH + lane];
        float aA, axA, aB, axB;
        gather_hx(g_h, Xt, nA, lane, lo, cx, aA, axA);
        gather_hx(g_h, Xt, nB, lane, lo, cx, aB, axB);

        s_st[wid][0][lane] = hA;  s_st[wid][1][lane] = aA;
        s_st[wid][2][lane] = hB;  s_st[wid][3][lane] = aB;
        if (lo) {
            // packed x vector: [0..15]=x, [16..31]=agg(x)
            s_st[wid][4][cx]      = Xt[nA * CIN + cx];
            s_st[wid][4][16 + cx] = axA;
            s_st[wid][5][cx]      = Xt[nB * CIN + cx];
            s_st[wid][5][16 + cx] = axB;
            g_AXs[nA * CIN + cx] = axA;     // for k_gru_b
            g_AXs[nB * CIN + cx] = axB;
        }
        __syncwarp();

        float zA = s_bz[lane], rA = s_br[lane];
        float zB = zA,         rB = rA;

        const float4* hAp = (const float4*)&s_st[wid][0][0];
        const float4* aAp = (const float4*)&s_st[wid][1][0];
        const float4* hBp = (const float4*)&s_st[wid][2][0];
        const float4* aBp = (const float4*)&s_st[wid][3][0];
        const float4* xAp = (const float4*)&s_st[wid][4][0];
        const float4* xBp = (const float4*)&s_st[wid][5][0];

#pragma unroll
        for (int c4 = 0; c4 < 4; c4++) {
            float4 x4A = xAp[c4], ax4A = xAp[4 + c4];
            float4 x4B = xBp[c4], ax4B = xBp[4 + c4];
#pragma unroll
            for (int u = 0; u < 4; u++) {
                float4 w = s_wx[(c4 * 4 + u) * CH + lane];
                float xa = GETC(x4A, u), aa = GETC(ax4A, u);
                float xb = GETC(x4B, u), ab = GETC(ax4B, u);
                zA += xa * w.x + aa * w.y;  rA += xa * w.z + aa * w.w;
                zB += xb * w.x + ab * w.y;  rB += xb * w.z + ab * w.w;
            }
        }
#pragma unroll
        for (int c4 = 0; c4 < 8; c4++) {
            float4 h4A = hAp[c4], a4A = aAp[c4];
            float4 h4B = hBp[c4], a4B = aBp[c4];
#pragma unroll
            for (int u = 0; u < 4; u++) {
                float4 w = s_wh[(c4 * 4 + u) * CH + lane];
                float ha = GETC(h4A, u), aa = GETC(a4A, u);
                float hb = GETC(h4B, u), ab = GETC(a4B, u);
                zA += ha * w.x + aa * w.y;  rA += ha * w.z + aa * w.w;
                zB += hb * w.x + ab * w.y;  rB += hb * w.z + ab * w.w;
            }
        }
        zA = 1.f / (1.f + __expf(-zA));
        rA = 1.f / (1.f + __expf(-rA));
        zB = 1.f / (1.f + __expf(-zB));
        rB = 1.f / (1.f + __expf(-rB));
        g_Z [nA * CH + lane] = zA;  g_hR[nA * CH + lane] = hA * rA;
        g_Z [nB * CH + lane] = zB;  g_hR[nB * CH + lane] = hB * rB;
        __syncwarp();
    }
}

__global__ void __launch_bounds__(256, 4) k_gru_b(
    int t, const float* __restrict__ X,
    const float* __restrict__ Wxh, const float* __restrict__ bxh,
    const float* __restrict__ Whh, const float* __restrict__ bhh,
    const float* __restrict__ fcw, const float* __restrict__ fcb,
    float* __restrict__ out)
{
    __shared__ float2 s_wx[CIN * CH];   // {wxh0, wxh1}
    __shared__ float2 s_wh[CH * CH];    // {whh0, whh1}
    __shared__ float  s_fcw[CH * COUTC];
    __shared__ float  s_bh[CH];
    __shared__ float  s_fcb[COUTC];
    __shared__ __align__(16) float s_st[8][8][CH];  // [hrA,aA,hrB,aB,xpA,xpB,hnA,hnB]
    int tid = threadIdx.x;
    for (int i = tid; i < CIN * CH; i += 256)
        s_wx[i] = make_float2(Wxh[i], Wxh[CIN * CH + i]);
    for (int i = tid; i < CH * CH; i += 256)
        s_wh[i] = make_float2(Whh[i], Whh[CH * CH + i]);
    for (int i = tid; i < CH * COUTC; i += 256) s_fcw[i] = fcw[i];
    if (tid < CH)    s_bh[tid]  = bxh[tid] + bhh[tid];
    if (tid < COUTC) s_fcb[tid] = fcb[tid];
    __syncthreads();

    const float* Xt = X + (size_t)t * NN * CIN;
    int lane = tid & 31, wid = tid >> 5;
    int cx = lane & 15;
    int gw = blockIdx.x * 8 + wid, nw = gridDim.x * 8;
    for (int p = gw; p < NN / 2; p += nw) {
        int nA = 2 * p, nB = 2 * p + 1;
        float hA  = g_h [nA * CH + lane];
        float hB  = g_h [nB * CH + lane];
        float hrA = g_hR[nA * CH + lane];
        float hrB = g_hR[nB * CH + lane];
        float zA  = g_Z [nA * CH + lane];
        float zB  = g_Z [nB * CH + lane];
        float xpA, xpB;
        if (lane < 16) {
            xpA = Xt[nA * CIN + cx];
            xpB = Xt[nB * CIN + cx];
        } else {
            xpA = g_AXs[nA * CIN + cx];
            xpB = g_AXs[nB * CIN + cx];
        }
        float aA = gather_h(g_hR, nA, lane);
        float aB = gather_h(g_hR, nB, lane);

        s_st[wid][0][lane] = hrA; s_st[wid][1][lane] = aA;
        s_st[wid][2][lane] = hrB; s_st[wid][3][lane] = aB;
        s_st[wid][4][lane] = xpA; s_st[wid][5][lane] = xpB;
        __syncwarp();

        float cA = s_bh[lane], cB = cA;
        const float4* hAp = (const float4*)&s_st[wid][0][0];
        const float4* aAp = (const float4*)&s_st[wid][1][0];
        const float4* hBp = (const float4*)&s_st[wid][2][0];
        const float4* aBp = (const float4*)&s_st[wid][3][0];
        const float4* xAp = (const float4*)&s_st[wid][4][0];
        const float4* xBp = (const float4*)&s_st[wid][5][0];

#pragma unroll
        for (int c4 = 0; c4 < 4; c4++) {
            float4 x4A = xAp[c4], ax4A = xAp[4 + c4];
            float4 x4B = xBp[c4], ax4B = xBp[4 + c4];
#pragma unroll
            for (int u = 0; u < 4; u++) {
                float2 w = s_wx[(c4 * 4 + u) * CH + lane];
                cA += GETC(x4A, u) * w.x + GETC(ax4A, u) * w.y;
                cB += GETC(x4B, u) * w.x + GETC(ax4B, u) * w.y;
            }
        }
#pragma unroll
        for (int c4 = 0; c4 < 8; c4++) {
            float4 h4A = hAp[c4], a4A = aAp[c4];
            float4 h4B = hBp[c4], a4B = aBp[c4];
#pragma unroll
            for (int u = 0; u < 4; u++) {
                float2 w = s_wh[(c4 * 4 + u) * CH + lane];
                cA += GETC(h4A, u) * w.x + GETC(a4A, u) * w.y;
                cB += GETC(h4B, u) * w.x + GETC(a4B, u) * w.y;
            }
        }
        float hnA = zA * hA + (1.f - zA) * tanhf(cA);
        float hnB = zB * hB + (1.f - zB) * tanhf(cB);
        g_h[nA * CH + lane] = hnA;
        g_h[nB * CH + lane] = hnB;

        // out = hn @ fc_w + fc_b : lanes 0..7 -> node A, lanes 8..15 -> node B
        s_st[wid][6][lane] = hnA;
        s_st[wid][7][lane] = hnB;
        __syncwarp();
        if (lane < 16) {
            int node = lane >> 3, j = lane & 7;
            const float* hn = &s_st[wid][6 + node][0];
            float acc = s_fcb[j];
#pragma unroll
            for (int c = 0; c < CH; c++) acc += hn[c] * s_fcw[c * COUTC + j];
            int n = node ? nB : nA;
            out[((size_t)t * NN + n) * COUTC + j] = acc;
        }
        __syncwarp();
    }
}

// ---------------- launch ----------------
extern "C" void kernel_launch(void* const* d_in, const int* in_sizes, int n_in,
                              void* d_out, int out_size) {
    const float* X   = (const float*)d_in[0];
    const void*  ei  = d_in[1];
    const float* Wxz = (const float*)d_in[2];
    const float* bxz = (const float*)d_in[3];
    const float* Whz = (const float*)d_in[4];
    const float* bhz = (const float*)d_in[5];
    const float* Wxr = (const float*)d_in[6];
    const float* bxr = (const float*)d_in[7];
    const float* Whr = (const float*)d_in[8];
    const float* bhr = (const float*)d_in[9];
    const float* Wxh = (const float*)d_in[10];
    const float* bxh = (const float*)d_in[11];
    const float* Whh = (const float*)d_in[12];
    const float* bhh = (const float*)d_in[13];
    const float* fcw = (const float*)d_in[14];
    const float* fcb = (const float*)d_in[15];
    float* out = (float*)d_out;

    int E = in_sizes[1] / 2;

    // preprocess: exactly 3 launches so first k_gru_a is launch index 3 (ncu)
    k_zero<<<2048, 256>>>(ei);
    k_prep<<<1, 1024>>>(ei, E);
    k_fill<<<(E + 255) / 256, 256>>>(ei, E);

    // sequential GRU recurrence (agg(x_t) fused into k_gru_a)
    for (int t = 0; t < TT; t++) {
        k_gru_a<<<592, 256>>>(t, X, Wxz, bxz, Whz, bhz, Wxr, bxr, Whr, bhr);
        k_gru_b<<<592, 256>>>(t, X, Wxh, bxh, Whh, bhh, fcw, fcb, out);
    }
}